// round 2
// baseline (speedup 1.0000x reference)
#include <cuda_runtime.h>
#include <cuda_bf16.h>

// Problem constants (fixed by the dataset: B=8192, D=128)
#define NB   8192
#define ND   128
#define BI   128
#define BJ   128
#define KD   128
#define PITCH 132          // padded row pitch (floats) for transposed smem tiles
#define NSPLIT 4           // j-dimension split across blockIdx.y
#define MARGIN 0.5f

// Scratch (device globals: no allocation allowed)
__device__ float g_anorm[NB * ND];
__device__ float g_posd[NB];
__device__ int   g_lab[NB];
__device__ int   g_maxbits[NB];   // bits of (max_gram + 2.0f), clamped >= 0 -> positive-float int ordering

// ---------------------------------------------------------------------------
// Kernel 1: normalize anchor rows, compute pos_dist = ||a_n - p_n||^2,
// copy labels (int32 on device: JAX x64 is disabled, so "int64" is int32),
// init max accumulator. One warp per row.
// ---------------------------------------------------------------------------
__global__ void prep_kernel(const float* __restrict__ anchor,
                            const float* __restrict__ positive,
                            const int* __restrict__ labels) {
    int gwarp = (blockIdx.x * blockDim.x + threadIdx.x) >> 5;
    int lane  = threadIdx.x & 31;
    if (gwarp >= NB) return;

    const float4* arow = reinterpret_cast<const float4*>(anchor  + (size_t)gwarp * ND);
    const float4* prow = reinterpret_cast<const float4*>(positive + (size_t)gwarp * ND);
    float4 av = arow[lane];
    float4 pv = prow[lane];

    float sa = av.x*av.x + av.y*av.y + av.z*av.z + av.w*av.w;
    float sp = pv.x*pv.x + pv.y*pv.y + pv.z*pv.z + pv.w*pv.w;
    #pragma unroll
    for (int o = 16; o > 0; o >>= 1) {
        sa += __shfl_xor_sync(0xffffffffu, sa, o);
        sp += __shfl_xor_sync(0xffffffffu, sp, o);
    }
    float inva = 1.0f / fmaxf(sqrtf(sa), 1e-12f);
    float invp = 1.0f / fmaxf(sqrtf(sp), 1e-12f);

    float4 an;
    an.x = av.x * inva; an.y = av.y * inva; an.z = av.z * inva; an.w = av.w * inva;
    reinterpret_cast<float4*>(g_anorm + (size_t)gwarp * ND)[lane] = an;

    float dx = an.x - pv.x * invp;
    float dy = an.y - pv.y * invp;
    float dz = an.z - pv.z * invp;
    float dw = an.w - pv.w * invp;
    float d2 = dx*dx + dy*dy + dz*dz + dw*dw;
    #pragma unroll
    for (int o = 16; o > 0; o >>= 1)
        d2 += __shfl_xor_sync(0xffffffffu, d2, o);

    if (lane == 0) {
        g_posd[gwarp]    = d2;
        g_lab[gwarp]     = labels[gwarp];
        g_maxbits[gwarp] = 0;   // == bits of 0.0f; all real entries are >= 1.0f after +2 shift
    }
}

// ---------------------------------------------------------------------------
// Kernel 2: fused max-gram. Each block: 128 rows (i-tile) x one j-chunk of
// 8192/NSPLIT columns, tiled by 128. 8x8 register tiles per thread, full
// K=128 in shared memory (transposed, padded). Label mask applied per tile;
// per-row running max combined via atomicMax on positive-shifted float bits.
// ---------------------------------------------------------------------------
__global__ void __launch_bounds__(256, 1)
maxgram_kernel() {
    extern __shared__ float sm[];
    float* As = sm;                 // [KD][PITCH]
    float* Bs = sm + KD * PITCH;    // [KD][PITCH]
    __shared__ int labI[BI];
    __shared__ int labJ[BJ];

    const int tid = threadIdx.x;
    const int i0  = blockIdx.x * BI;

    // Load A tile transposed: As[k][i]
    #pragma unroll 4
    for (int idx = tid; idx < BI * (KD / 4); idx += 256) {
        int r  = idx >> 5;          // row within tile (KD/4 = 32 float4 per row)
        int c4 = idx & 31;
        float4 v = *reinterpret_cast<const float4*>(g_anorm + (size_t)(i0 + r) * ND + c4 * 4);
        As[(c4*4 + 0) * PITCH + r] = v.x;
        As[(c4*4 + 1) * PITCH + r] = v.y;
        As[(c4*4 + 2) * PITCH + r] = v.z;
        As[(c4*4 + 3) * PITCH + r] = v.w;
    }
    if (tid < BI) labI[tid] = g_lab[i0 + tid];

    const int ty = tid >> 4;        // 0..15 -> i micro-tile
    const int tx = tid & 15;        // 0..15 -> j micro-tile

    float mx[8];
    #pragma unroll
    for (int i = 0; i < 8; i++) mx[i] = -3.0f;

    const int jchunk = NB / NSPLIT;
    const int jbase  = blockIdx.y * jchunk;

    for (int jt = 0; jt < jchunk / BJ; jt++) {
        const int j0 = jbase + jt * BJ;

        __syncthreads();   // previous iter done reading Bs / first iter: As stores done too
        #pragma unroll 4
        for (int idx = tid; idx < BJ * (KD / 4); idx += 256) {
            int r  = idx >> 5;
            int c4 = idx & 31;
            float4 v = *reinterpret_cast<const float4*>(g_anorm + (size_t)(j0 + r) * ND + c4 * 4);
            Bs[(c4*4 + 0) * PITCH + r] = v.x;
            Bs[(c4*4 + 1) * PITCH + r] = v.y;
            Bs[(c4*4 + 2) * PITCH + r] = v.z;
            Bs[(c4*4 + 3) * PITCH + r] = v.w;
        }
        if (tid < BJ) labJ[tid] = g_lab[j0 + tid];
        __syncthreads();

        float acc[8][8];
        #pragma unroll
        for (int a = 0; a < 8; a++)
            #pragma unroll
            for (int b = 0; b < 8; b++) acc[a][b] = 0.0f;

        #pragma unroll 4
        for (int k = 0; k < KD; k++) {
            const float* Ak = As + k * PITCH + ty * 8;
            const float* Bk = Bs + k * PITCH + tx * 8;
            float4 a0 = *reinterpret_cast<const float4*>(Ak);
            float4 a1 = *reinterpret_cast<const float4*>(Ak + 4);
            float4 b0 = *reinterpret_cast<const float4*>(Bk);
            float4 b1 = *reinterpret_cast<const float4*>(Bk + 4);
            float ar[8] = {a0.x, a0.y, a0.z, a0.w, a1.x, a1.y, a1.z, a1.w};
            float br[8] = {b0.x, b0.y, b0.z, b0.w, b1.x, b1.y, b1.z, b1.w};
            #pragma unroll
            for (int ii = 0; ii < 8; ii++)
                #pragma unroll
                for (int jj = 0; jj < 8; jj++)
                    acc[ii][jj] = fmaf(ar[ii], br[jj], acc[ii][jj]);
        }

        // label mask + running max
        #pragma unroll
        for (int ii = 0; ii < 8; ii++) {
            int myl = labI[ty * 8 + ii];
            #pragma unroll
            for (int jj = 0; jj < 8; jj++) {
                if (labJ[tx * 8 + jj] != myl)
                    mx[ii] = fmaxf(mx[ii], acc[ii][jj]);
            }
        }
    }

    // Reduce across the 16 tx lanes of each ty group (xor <=8 stays in 16-lane half)
    #pragma unroll
    for (int ii = 0; ii < 8; ii++) {
        float v = mx[ii];
        #pragma unroll
        for (int o = 8; o > 0; o >>= 1)
            v = fmaxf(v, __shfl_xor_sync(0xffffffffu, v, o));
        if (tx == 0) {
            int bits = __float_as_int(fmaxf(v + 2.0f, 0.0f));
            atomicMax(&g_maxbits[i0 + ty * 8 + ii], bits);
        }
    }
}

// ---------------------------------------------------------------------------
// Kernel 3: final loss reduction (single block, deterministic).
// ---------------------------------------------------------------------------
__global__ void finalize_kernel(float* __restrict__ out) {
    __shared__ float red[256];
    float s = 0.0f;
    for (int i = threadIdx.x; i < NB; i += 256) {
        float g   = __int_as_float(g_maxbits[i]) - 2.0f;  // max gram among different labels
        float neg = fmaxf(2.0f - 2.0f * g, 0.0f);          // min squared distance
        float l   = g_posd[i] - neg + MARGIN;
        s += fmaxf(l, 0.0f);
    }
    red[threadIdx.x] = s;
    __syncthreads();
    #pragma unroll
    for (int stride = 128; stride > 0; stride >>= 1) {
        if (threadIdx.x < stride) red[threadIdx.x] += red[threadIdx.x + stride];
        __syncthreads();
    }
    if (threadIdx.x == 0) out[0] = red[0] / (float)NB;
}

extern "C" void kernel_launch(void* const* d_in, const int* in_sizes, int n_in,
                              void* d_out, int out_size) {
    const float* anchor   = (const float*)d_in[0];
    const float* positive = (const float*)d_in[1];
    const int*   labels   = (const int*)d_in[2];   // JAX x64 disabled: int64 request -> int32
    float*       out      = (float*)d_out;

    // Kernel 1: one warp per row -> 8 rows per 256-thread block
    prep_kernel<<<NB / 8, 256>>>(anchor, positive, labels);

    // Kernel 2: big smem
    const int smem = 2 * KD * PITCH * sizeof(float);   // 135168 B
    cudaFuncSetAttribute(maxgram_kernel, cudaFuncAttributeMaxDynamicSharedMemorySize, smem);
    dim3 grid(NB / BI, NSPLIT);
    maxgram_kernel<<<grid, 256, smem>>>();

    // Kernel 3
    finalize_kernel<<<1, 256>>>(out);
}

// round 4
// speedup vs baseline: 3.5032x; 3.5032x over previous
#include <cuda_runtime.h>
#include <cuda_bf16.h>
#include <cstdint>

// Problem constants (fixed: B=8192, D=128)
#define NB 8192
#define ND 128
#define BI 128
#define BJ 128
#define NJSPLIT 2
#define MARGIN 0.5f
#define STRB 272                    // padded row stride in bytes (136 bf16) -> conflict-free LDS
#define TILE_BYTES (128 * STRB)     // 34816 per 128x128 bf16 tile

// Device scratch (no allocation allowed)
__device__ __align__(16) __nv_bfloat16 g_ahi[NB * ND];
__device__ __align__(16) __nv_bfloat16 g_alo[NB * ND];
__device__ float g_posd[NB];
__device__ int   g_lab[NB];
__device__ int   g_maxbits[NB];

// ---------------------------------------------------------------------------
// helpers
// ---------------------------------------------------------------------------
__device__ __forceinline__ uint32_t smem_u32(const void* p) {
    uint32_t a;
    asm("{ .reg .u64 t; cvta.to.shared.u64 t, %1; cvt.u32.u64 %0, t; }" : "=r"(a) : "l"(p));
    return a;
}
__device__ __forceinline__ void cpasync16(uint32_t dst, const void* src) {
    asm volatile("cp.async.cg.shared.global [%0], [%1], 16;" :: "r"(dst), "l"(src));
}
__device__ __forceinline__ void mma16816(float* c, const uint32_t* a, const uint32_t* b) {
    asm volatile(
        "mma.sync.aligned.m16n8k16.row.col.f32.bf16.bf16.f32 "
        "{%0,%1,%2,%3}, {%4,%5,%6,%7}, {%8,%9}, {%0,%1,%2,%3};"
        : "+f"(c[0]), "+f"(c[1]), "+f"(c[2]), "+f"(c[3])
        : "r"(a[0]), "r"(a[1]), "r"(a[2]), "r"(a[3]), "r"(b[0]), "r"(b[1]));
}

// ---------------------------------------------------------------------------
// Kernel 1: normalize anchors -> bf16 hi/lo split; pos_dist; labels; init max.
// One warp per row.
// ---------------------------------------------------------------------------
__global__ void prep_kernel(const float* __restrict__ anchor,
                            const float* __restrict__ positive,
                            const int* __restrict__ labels) {
    int row  = (blockIdx.x * blockDim.x + threadIdx.x) >> 5;
    int lane = threadIdx.x & 31;
    if (row >= NB) return;

    float4 av = reinterpret_cast<const float4*>(anchor   + (size_t)row * ND)[lane];
    float4 pv = reinterpret_cast<const float4*>(positive + (size_t)row * ND)[lane];

    float sa = av.x*av.x + av.y*av.y + av.z*av.z + av.w*av.w;
    float sp = pv.x*pv.x + pv.y*pv.y + pv.z*pv.z + pv.w*pv.w;
    #pragma unroll
    for (int o = 16; o > 0; o >>= 1) {
        sa += __shfl_xor_sync(0xffffffffu, sa, o);
        sp += __shfl_xor_sync(0xffffffffu, sp, o);
    }
    float inva = 1.0f / fmaxf(sqrtf(sa), 1e-12f);
    float invp = 1.0f / fmaxf(sqrtf(sp), 1e-12f);

    float an[4] = {av.x*inva, av.y*inva, av.z*inva, av.w*inva};
    float pn[4] = {pv.x*invp, pv.y*invp, pv.z*invp, pv.w*invp};

    __nv_bfloat16 hi[4], lo[4];
    #pragma unroll
    for (int q = 0; q < 4; q++) {
        hi[q] = __float2bfloat16_rn(an[q]);
        lo[q] = __float2bfloat16_rn(an[q] - __bfloat162float(hi[q]));
    }
    size_t base = (size_t)row * ND + lane * 4;
    __nv_bfloat162 h01; h01.x = hi[0]; h01.y = hi[1];
    __nv_bfloat162 h23; h23.x = hi[2]; h23.y = hi[3];
    __nv_bfloat162 l01; l01.x = lo[0]; l01.y = lo[1];
    __nv_bfloat162 l23; l23.x = lo[2]; l23.y = lo[3];
    reinterpret_cast<__nv_bfloat162*>(g_ahi + base)[0] = h01;
    reinterpret_cast<__nv_bfloat162*>(g_ahi + base)[1] = h23;
    reinterpret_cast<__nv_bfloat162*>(g_alo + base)[0] = l01;
    reinterpret_cast<__nv_bfloat162*>(g_alo + base)[1] = l23;

    float d2 = 0.0f;
    #pragma unroll
    for (int q = 0; q < 4; q++) {
        float d = an[q] - pn[q];
        d2 = fmaf(d, d, d2);
    }
    #pragma unroll
    for (int o = 16; o > 0; o >>= 1)
        d2 += __shfl_xor_sync(0xffffffffu, d2, o);

    if (lane == 0) {
        g_posd[row]    = d2;
        g_lab[row]     = labels[row];
        g_maxbits[row] = 0;
    }
}

// ---------------------------------------------------------------------------
// Kernel 2: max-gram via mma.sync (bf16 split precision, fp32 accumulate).
// SMEM dyn layout: [A hi][A lo][B0 hi][B0 lo][B1 hi][B1 lo], each 34816 B,
// rows padded to 272 B so fragment LDS.b32 loads are bank-conflict-free.
// Warp grid 2(M) x 4(N): each warp owns 64 rows x 32 cols of the 128x128 tile.
// ---------------------------------------------------------------------------
__global__ void __launch_bounds__(256, 1) maxgram_mma() {
    extern __shared__ char dsm[];
    __shared__ int labJ[2][BJ];

    const int tid  = threadIdx.x;
    const int lane = tid & 31;
    const int wid  = tid >> 5;
    const int wm   = wid & 1;         // 0..1 : M half
    const int wn   = wid >> 1;        // 0..3 : N quarter
    const int g    = lane >> 2;       // groupID 0..7
    const int q    = lane & 3;

    const int i0    = blockIdx.x * BI;
    const int jbase = blockIdx.y * (NB / NJSPLIT);
    const int NCH   = (NB / NJSPLIT) / BJ;

    const uint32_t smb = smem_u32(dsm);
    const int ALO_OFF = TILE_BYTES;
    const int BB0     = 2 * TILE_BYTES;

    // ---- load A tile (hi + lo), padded rows ----
    for (int idx = tid; idx < 2048; idx += 256) {
        int r = idx >> 4, c = idx & 15;
        *reinterpret_cast<uint4*>(dsm + r * STRB + c * 16) =
            *reinterpret_cast<const uint4*>(g_ahi + (size_t)(i0 + r) * ND + c * 8);
        *reinterpret_cast<uint4*>(dsm + ALO_OFF + r * STRB + c * 16) =
            *reinterpret_cast<const uint4*>(g_alo + (size_t)(i0 + r) * ND + c * 8);
    }

    // my row labels (8 per thread)
    int lr[4][2];
    #pragma unroll
    for (int mt = 0; mt < 4; mt++) {
        int r = i0 + wm * 64 + mt * 16 + g;
        lr[mt][0] = g_lab[r];
        lr[mt][1] = g_lab[r + 8];
    }

    // ---- prologue: chunk 0 B via cp.async ----
    {
        const int j0 = jbase;
        for (int idx = tid; idx < 2048; idx += 256) {
            int r = idx >> 4, c = idx & 15;
            uint32_t d = smb + BB0 + r * STRB + c * 16;
            cpasync16(d,              g_ahi + (size_t)(j0 + r) * ND + c * 8);
            cpasync16(d + TILE_BYTES, g_alo + (size_t)(j0 + r) * ND + c * 8);
        }
        if (tid < BJ) labJ[0][tid] = g_lab[j0 + tid];
        asm volatile("cp.async.commit_group;");
        asm volatile("cp.async.wait_group 0;" ::: "memory");
    }
    __syncthreads();

    float mx[4][2];
    #pragma unroll
    for (int mt = 0; mt < 4; mt++) { mx[mt][0] = -3.0f; mx[mt][1] = -3.0f; }

    for (int c = 0; c < NCH; c++) {
        const int buf = c & 1, nb = buf ^ 1;

        // kick off next chunk's B loads (async, overlaps compute)
        if (c + 1 < NCH) {
            const int j0 = jbase + (c + 1) * BJ;
            const uint32_t bb = smb + BB0 + nb * 2 * TILE_BYTES;
            for (int idx = tid; idx < 2048; idx += 256) {
                int r = idx >> 4, cc = idx & 15;
                uint32_t d = bb + r * STRB + cc * 16;
                cpasync16(d,              g_ahi + (size_t)(j0 + r) * ND + cc * 8);
                cpasync16(d + TILE_BYTES, g_alo + (size_t)(j0 + r) * ND + cc * 8);
            }
            if (tid < BJ) labJ[nb][tid] = g_lab[j0 + tid];
            asm volatile("cp.async.commit_group;");
        }

        // ---- compute chunk c ----
        const char* Bhi = dsm + BB0 + buf * 2 * TILE_BYTES;
        float acc[4][4][4];
        #pragma unroll
        for (int mt = 0; mt < 4; mt++)
            #pragma unroll
            for (int nt = 0; nt < 4; nt++)
                #pragma unroll
                for (int e = 0; e < 4; e++) acc[mt][nt][e] = 0.0f;

        #pragma unroll
        for (int ks = 0; ks < 8; ks++) {
            const int kb = (ks * 16 + q * 2) * 2;   // byte offset of this lane's k0

            uint32_t ah[4][4], al[4][4];
            #pragma unroll
            for (int mt = 0; mt < 4; mt++) {
                const char* pa = dsm + (wm * 64 + mt * 16 + g) * STRB + kb;
                ah[mt][0] = *reinterpret_cast<const uint32_t*>(pa);
                ah[mt][1] = *reinterpret_cast<const uint32_t*>(pa + 8 * STRB);
                ah[mt][2] = *reinterpret_cast<const uint32_t*>(pa + 16);
                ah[mt][3] = *reinterpret_cast<const uint32_t*>(pa + 8 * STRB + 16);
                const char* pl = pa + TILE_BYTES;
                al[mt][0] = *reinterpret_cast<const uint32_t*>(pl);
                al[mt][1] = *reinterpret_cast<const uint32_t*>(pl + 8 * STRB);
                al[mt][2] = *reinterpret_cast<const uint32_t*>(pl + 16);
                al[mt][3] = *reinterpret_cast<const uint32_t*>(pl + 8 * STRB + 16);
            }
            uint32_t bh[4][2], bl[4][2];
            #pragma unroll
            for (int nt = 0; nt < 4; nt++) {
                const char* pb = Bhi + (wn * 32 + nt * 8 + g) * STRB + kb;
                bh[nt][0] = *reinterpret_cast<const uint32_t*>(pb);
                bh[nt][1] = *reinterpret_cast<const uint32_t*>(pb + 16);
                const char* pbl = pb + TILE_BYTES;
                bl[nt][0] = *reinterpret_cast<const uint32_t*>(pbl);
                bl[nt][1] = *reinterpret_cast<const uint32_t*>(pbl + 16);
            }
            #pragma unroll
            for (int mt = 0; mt < 4; mt++)
                #pragma unroll
                for (int nt = 0; nt < 4; nt++) {
                    mma16816(acc[mt][nt], ah[mt], bh[nt]);   // hi*hi
                    mma16816(acc[mt][nt], ah[mt], bl[nt]);   // hi*lo
                    mma16816(acc[mt][nt], al[mt], bh[nt]);   // lo*hi
                }
        }

        // ---- epilogue: label mask + running max ----
        #pragma unroll
        for (int nt = 0; nt < 4; nt++) {
            int c0 = wn * 32 + nt * 8 + q * 2;
            int l0 = labJ[buf][c0], l1 = labJ[buf][c0 + 1];
            #pragma unroll
            for (int mt = 0; mt < 4; mt++) {
                float v;
                v = (l0 == lr[mt][0]) ? -3.0f : acc[mt][nt][0]; mx[mt][0] = fmaxf(mx[mt][0], v);
                v = (l1 == lr[mt][0]) ? -3.0f : acc[mt][nt][1]; mx[mt][0] = fmaxf(mx[mt][0], v);
                v = (l0 == lr[mt][1]) ? -3.0f : acc[mt][nt][2]; mx[mt][1] = fmaxf(mx[mt][1], v);
                v = (l1 == lr[mt][1]) ? -3.0f : acc[mt][nt][3]; mx[mt][1] = fmaxf(mx[mt][1], v);
            }
        }

        if (c + 1 < NCH) asm volatile("cp.async.wait_group 0;" ::: "memory");
        __syncthreads();
    }

    // reduce across the 4 q-lanes sharing each row, then merge globally
    #pragma unroll
    for (int mt = 0; mt < 4; mt++)
        #pragma unroll
        for (int r = 0; r < 2; r++) {
            float v = mx[mt][r];
            v = fmaxf(v, __shfl_xor_sync(0xffffffffu, v, 1));
            v = fmaxf(v, __shfl_xor_sync(0xffffffffu, v, 2));
            if (q == 0)
                atomicMax(&g_maxbits[i0 + wm * 64 + mt * 16 + g + r * 8],
                          __float_as_int(fmaxf(v + 2.0f, 0.0f)));
        }
}

// ---------------------------------------------------------------------------
// Kernel 3: final loss reduction.
// ---------------------------------------------------------------------------
__global__ void finalize_kernel(float* __restrict__ out) {
    __shared__ float red[256];
    float s = 0.0f;
    for (int i = threadIdx.x; i < NB; i += 256) {
        float gmax = __int_as_float(g_maxbits[i]) - 2.0f;
        float neg  = fmaxf(2.0f - 2.0f * gmax, 0.0f);
        float l    = g_posd[i] - neg + MARGIN;
        s += fmaxf(l, 0.0f);
    }
    red[threadIdx.x] = s;
    __syncthreads();
    #pragma unroll
    for (int stride = 128; stride > 0; stride >>= 1) {
        if (threadIdx.x < stride) red[threadIdx.x] += red[threadIdx.x + stride];
        __syncthreads();
    }
    if (threadIdx.x == 0) out[0] = red[0] / (float)NB;
}

extern "C" void kernel_launch(void* const* d_in, const int* in_sizes, int n_in,
                              void* d_out, int out_size) {
    const float* anchor   = (const float*)d_in[0];
    const float* positive = (const float*)d_in[1];
    const int*   labels   = (const int*)d_in[2];   // JAX x64 disabled: int64 -> int32
    float*       out      = (float*)d_out;

    prep_kernel<<<NB / 8, 256>>>(anchor, positive, labels);

    const int smem = 6 * TILE_BYTES;   // 208896 B
    cudaFuncSetAttribute(maxgram_mma, cudaFuncAttributeMaxDynamicSharedMemorySize, smem);
    dim3 grid(NB / BI, NJSPLIT);
    maxgram_mma<<<grid, 256, smem>>>();

    finalize_kernel<<<1, 256>>>(out);
}

// round 5
// speedup vs baseline: 5.5050x; 1.5714x over previous
#include <cuda_runtime.h>
#include <cuda_bf16.h>
#include <cstdint>

// Problem constants (fixed: B=8192, D=128)
#define NB 8192
#define ND 128
#define NTILE 64                    // 8192 / 128 tile rows
#define TOTTILES 2080               // NTILE*(NTILE+1)/2
#define GRID 130
#define TPC 16                      // tiles per CTA: 130*16 = 2080
#define MARGIN 0.5f
#define STRB 272                    // padded row stride in bytes -> conflict-free LDS
#define TILE_BYTES (128 * STRB)     // 34816 per 128x128 bf16 tile

// Device scratch (no allocation allowed)
__device__ __align__(16) __nv_bfloat16 g_ahi[NB * ND];
__device__ __align__(16) __nv_bfloat16 g_alo[NB * ND];
__device__ float g_posd[NB];
__device__ int   g_lab[NB];
__device__ int   g_maxbits[NB];

// ---------------------------------------------------------------------------
// helpers
// ---------------------------------------------------------------------------
__device__ __forceinline__ uint32_t smem_u32(const void* p) {
    uint32_t a;
    asm("{ .reg .u64 t; cvta.to.shared.u64 t, %1; cvt.u32.u64 %0, t; }" : "=r"(a) : "l"(p));
    return a;
}
__device__ __forceinline__ void cpasync16(uint32_t dst, const void* src) {
    asm volatile("cp.async.cg.shared.global [%0], [%1], 16;" :: "r"(dst), "l"(src));
}
__device__ __forceinline__ void mma16816(float* c, const uint32_t* a, const uint32_t* b) {
    asm volatile(
        "mma.sync.aligned.m16n8k16.row.col.f32.bf16.bf16.f32 "
        "{%0,%1,%2,%3}, {%4,%5,%6,%7}, {%8,%9}, {%0,%1,%2,%3};"
        : "+f"(c[0]), "+f"(c[1]), "+f"(c[2]), "+f"(c[3])
        : "r"(a[0]), "r"(a[1]), "r"(a[2]), "r"(a[3]), "r"(b[0]), "r"(b[1]));
}

// ---------------------------------------------------------------------------
// Kernel 1: normalize anchors -> bf16 hi/lo split; pos_dist; labels; init max.
// ---------------------------------------------------------------------------
__global__ void prep_kernel(const float* __restrict__ anchor,
                            const float* __restrict__ positive,
                            const int* __restrict__ labels) {
    int row  = (blockIdx.x * blockDim.x + threadIdx.x) >> 5;
    int lane = threadIdx.x & 31;
    if (row >= NB) return;

    float4 av = reinterpret_cast<const float4*>(anchor   + (size_t)row * ND)[lane];
    float4 pv = reinterpret_cast<const float4*>(positive + (size_t)row * ND)[lane];

    float sa = av.x*av.x + av.y*av.y + av.z*av.z + av.w*av.w;
    float sp = pv.x*pv.x + pv.y*pv.y + pv.z*pv.z + pv.w*pv.w;
    #pragma unroll
    for (int o = 16; o > 0; o >>= 1) {
        sa += __shfl_xor_sync(0xffffffffu, sa, o);
        sp += __shfl_xor_sync(0xffffffffu, sp, o);
    }
    float inva = 1.0f / fmaxf(sqrtf(sa), 1e-12f);
    float invp = 1.0f / fmaxf(sqrtf(sp), 1e-12f);

    float an[4] = {av.x*inva, av.y*inva, av.z*inva, av.w*inva};
    float pn[4] = {pv.x*invp, pv.y*invp, pv.z*invp, pv.w*invp};

    __nv_bfloat16 hi[4], lo[4];
    #pragma unroll
    for (int q = 0; q < 4; q++) {
        hi[q] = __float2bfloat16_rn(an[q]);
        lo[q] = __float2bfloat16_rn(an[q] - __bfloat162float(hi[q]));
    }
    size_t base = (size_t)row * ND + lane * 4;
    __nv_bfloat162 h01; h01.x = hi[0]; h01.y = hi[1];
    __nv_bfloat162 h23; h23.x = hi[2]; h23.y = hi[3];
    __nv_bfloat162 l01; l01.x = lo[0]; l01.y = lo[1];
    __nv_bfloat162 l23; l23.x = lo[2]; l23.y = lo[3];
    reinterpret_cast<__nv_bfloat162*>(g_ahi + base)[0] = h01;
    reinterpret_cast<__nv_bfloat162*>(g_ahi + base)[1] = h23;
    reinterpret_cast<__nv_bfloat162*>(g_alo + base)[0] = l01;
    reinterpret_cast<__nv_bfloat162*>(g_alo + base)[1] = l23;

    float d2 = 0.0f;
    #pragma unroll
    for (int q = 0; q < 4; q++) {
        float d = an[q] - pn[q];
        d2 = fmaf(d, d, d2);
    }
    #pragma unroll
    for (int o = 16; o > 0; o >>= 1)
        d2 += __shfl_xor_sync(0xffffffffu, d2, o);

    if (lane == 0) {
        g_posd[row]    = d2;
        g_lab[row]     = labels[row];
        g_maxbits[row] = 0;
    }
}

// ---------------------------------------------------------------------------
// Kernel 2: symmetric max-gram. Only upper-triangular 128x128 tiles computed;
// each off-diagonal tile feeds row-max (i side) AND column-max (j side).
// SMEM: [A hi][A lo][B0 hi][B0 lo][B1 hi][B1 lo], rows padded to 272 B.
// Warp grid 2(M) x 4(N). 130 CTAs x 16 tiles = 2080 tiles, one wave.
// ---------------------------------------------------------------------------
__global__ void __launch_bounds__(256, 1) maxgram_sym() {
    extern __shared__ char dsm[];
    __shared__ int labJ[2][128];

    const int tid  = threadIdx.x;
    const int lane = tid & 31;
    const int wid  = tid >> 5;
    const int wm   = wid & 1;
    const int wn   = wid >> 1;
    const int g    = lane >> 2;
    const int q    = lane & 3;

    const uint32_t smb = smem_u32(dsm);

    // decode starting tile (triangular row-major)
    int L = blockIdx.x * TPC;
    int ti = 0, base = 0;
    while (base + (NTILE - ti) <= L) { base += NTILE - ti; ti++; }
    int tj = ti + (L - base);

    auto loadA = [&](int t) {
        const int i0 = t * 128;
        for (int idx = tid; idx < 2048; idx += 256) {
            int r = idx >> 4, c = idx & 15;
            uint32_t d = smb + r * STRB + c * 16;
            cpasync16(d,              g_ahi + (size_t)(i0 + r) * ND + c * 8);
            cpasync16(d + TILE_BYTES, g_alo + (size_t)(i0 + r) * ND + c * 8);
        }
    };
    auto loadB = [&](int t, int buf) {
        const int j0 = t * 128;
        uint32_t bb = smb + (2 + 2 * buf) * TILE_BYTES;
        for (int idx = tid; idx < 2048; idx += 256) {
            int r = idx >> 4, c = idx & 15;
            uint32_t d = bb + r * STRB + c * 16;
            cpasync16(d,              g_ahi + (size_t)(j0 + r) * ND + c * 8);
            cpasync16(d + TILE_BYTES, g_alo + (size_t)(j0 + r) * ND + c * 8);
        }
        if (tid < 128) labJ[buf][tid] = g_lab[j0 + tid];
    };

    int lr[4][2];
    auto loadLr = [&](int t) {
        #pragma unroll
        for (int mt = 0; mt < 4; mt++) {
            int r = t * 128 + wm * 64 + mt * 16 + g;
            lr[mt][0] = g_lab[r];
            lr[mt][1] = g_lab[r + 8];
        }
    };

    float mx[4][2];
    #pragma unroll
    for (int mt = 0; mt < 4; mt++) { mx[mt][0] = -3.0f; mx[mt][1] = -3.0f; }

    auto flushRows = [&](int t) {
        #pragma unroll
        for (int mt = 0; mt < 4; mt++)
            #pragma unroll
            for (int r = 0; r < 2; r++) {
                float v = mx[mt][r];
                v = fmaxf(v, __shfl_xor_sync(0xffffffffu, v, 1));
                v = fmaxf(v, __shfl_xor_sync(0xffffffffu, v, 2));
                if (q == 0)
                    atomicMax(&g_maxbits[t * 128 + wm * 64 + mt * 16 + g + r * 8],
                              __float_as_int(fmaxf(v + 2.0f, 0.0f)));
                mx[mt][r] = -3.0f;
            }
    };

    // prologue: first A + first B
    loadA(ti);
    loadB(tj, 0);
    asm volatile("cp.async.commit_group;");
    loadLr(ti);

    for (int n = 0; n < TPC; n++) {
        const int buf = n & 1;

        // next tile coordinates (triangular walk)
        int ti_n = ti, tj_n = tj + 1;
        if (tj_n == NTILE) { ti_n = ti + 1; tj_n = ti_n; }

        asm volatile("cp.async.wait_group 0;" ::: "memory");
        __syncthreads();

        if (n + 1 < TPC) {
            loadB(tj_n, buf ^ 1);
            asm volatile("cp.async.commit_group;");
        }

        // ---- compute tile (ti, tj) ----
        const char* Bhi = dsm + (2 + 2 * buf) * TILE_BYTES;
        float acc[4][4][4];
        #pragma unroll
        for (int mt = 0; mt < 4; mt++)
            #pragma unroll
            for (int nt = 0; nt < 4; nt++)
                #pragma unroll
                for (int e = 0; e < 4; e++) acc[mt][nt][e] = 0.0f;

        #pragma unroll
        for (int ks = 0; ks < 8; ks++) {
            const int kb = (ks * 16 + q * 2) * 2;

            uint32_t ah[4][4], al[4][4];
            #pragma unroll
            for (int mt = 0; mt < 4; mt++) {
                const char* pa = dsm + (wm * 64 + mt * 16 + g) * STRB + kb;
                ah[mt][0] = *reinterpret_cast<const uint32_t*>(pa);
                ah[mt][1] = *reinterpret_cast<const uint32_t*>(pa + 8 * STRB);
                ah[mt][2] = *reinterpret_cast<const uint32_t*>(pa + 16);
                ah[mt][3] = *reinterpret_cast<const uint32_t*>(pa + 8 * STRB + 16);
                const char* pl = pa + TILE_BYTES;
                al[mt][0] = *reinterpret_cast<const uint32_t*>(pl);
                al[mt][1] = *reinterpret_cast<const uint32_t*>(pl + 8 * STRB);
                al[mt][2] = *reinterpret_cast<const uint32_t*>(pl + 16);
                al[mt][3] = *reinterpret_cast<const uint32_t*>(pl + 8 * STRB + 16);
            }
            uint32_t bh[4][2], bl[4][2];
            #pragma unroll
            for (int nt = 0; nt < 4; nt++) {
                const char* pb = Bhi + (wn * 32 + nt * 8 + g) * STRB + kb;
                bh[nt][0] = *reinterpret_cast<const uint32_t*>(pb);
                bh[nt][1] = *reinterpret_cast<const uint32_t*>(pb + 16);
                const char* pbl = pb + TILE_BYTES;
                bl[nt][0] = *reinterpret_cast<const uint32_t*>(pbl);
                bl[nt][1] = *reinterpret_cast<const uint32_t*>(pbl + 16);
            }
            #pragma unroll
            for (int mt = 0; mt < 4; mt++)
                #pragma unroll
                for (int nt = 0; nt < 4; nt++) {
                    mma16816(acc[mt][nt], ah[mt], bh[nt]);   // hi*hi
                    mma16816(acc[mt][nt], ah[mt], bl[nt]);   // hi*lo
                    mma16816(acc[mt][nt], al[mt], bh[nt]);   // lo*hi
                }
        }

        // ---- epilogue: mask, row-max, column-max ----
        float cmax[4][2];
        #pragma unroll
        for (int nt = 0; nt < 4; nt++) { cmax[nt][0] = -3.0f; cmax[nt][1] = -3.0f; }

        #pragma unroll
        for (int nt = 0; nt < 4; nt++) {
            int c0 = wn * 32 + nt * 8 + q * 2;
            int l0 = labJ[buf][c0], l1 = labJ[buf][c0 + 1];
            #pragma unroll
            for (int mt = 0; mt < 4; mt++) {
                float v0 = (l0 == lr[mt][0]) ? -3.0f : acc[mt][nt][0];
                float v1 = (l1 == lr[mt][0]) ? -3.0f : acc[mt][nt][1];
                float v2 = (l0 == lr[mt][1]) ? -3.0f : acc[mt][nt][2];
                float v3 = (l1 == lr[mt][1]) ? -3.0f : acc[mt][nt][3];
                mx[mt][0] = fmaxf(mx[mt][0], fmaxf(v0, v1));
                mx[mt][1] = fmaxf(mx[mt][1], fmaxf(v2, v3));
                cmax[nt][0] = fmaxf(cmax[nt][0], fmaxf(v0, v2));
                cmax[nt][1] = fmaxf(cmax[nt][1], fmaxf(v1, v3));
            }
        }

        if (ti != tj) {
            // column-side: reduce over g lanes, merge into g_maxbits[tj*128 + col]
            #pragma unroll
            for (int nt = 0; nt < 4; nt++)
                #pragma unroll
                for (int e = 0; e < 2; e++) {
                    float v = cmax[nt][e];
                    v = fmaxf(v, __shfl_xor_sync(0xffffffffu, v, 4));
                    v = fmaxf(v, __shfl_xor_sync(0xffffffffu, v, 8));
                    v = fmaxf(v, __shfl_xor_sync(0xffffffffu, v, 16));
                    if (g == 0)
                        atomicMax(&g_maxbits[tj * 128 + wn * 32 + nt * 8 + q * 2 + e],
                                  __float_as_int(fmaxf(v + 2.0f, 0.0f)));
                }
        }

        if (n + 1 < TPC) {
            if (ti_n != ti) {
                flushRows(ti);
                __syncthreads();          // all warps done reading A
                loadA(ti_n);
                asm volatile("cp.async.commit_group;");
                loadLr(ti_n);
            }
            ti = ti_n; tj = tj_n;
        }
    }
    flushRows(ti);
}

// ---------------------------------------------------------------------------
// Kernel 3: final loss reduction.
// ---------------------------------------------------------------------------
__global__ void finalize_kernel(float* __restrict__ out) {
    __shared__ float red[256];
    float s = 0.0f;
    for (int i = threadIdx.x; i < NB; i += 256) {
        float gmax = __int_as_float(g_maxbits[i]) - 2.0f;
        float neg  = fmaxf(2.0f - 2.0f * gmax, 0.0f);
        float l    = g_posd[i] - neg + MARGIN;
        s += fmaxf(l, 0.0f);
    }
    red[threadIdx.x] = s;
    __syncthreads();
    #pragma unroll
    for (int stride = 128; stride > 0; stride >>= 1) {
        if (threadIdx.x < stride) red[threadIdx.x] += red[threadIdx.x + stride];
        __syncthreads();
    }
    if (threadIdx.x == 0) out[0] = red[0] / (float)NB;
}

extern "C" void kernel_launch(void* const* d_in, const int* in_sizes, int n_in,
                              void* d_out, int out_size) {
    const float* anchor   = (const float*)d_in[0];
    const float* positive = (const float*)d_in[1];
    const int*   labels   = (const int*)d_in[2];   // JAX x64 disabled: int64 -> int32
    float*       out      = (float*)d_out;

    prep_kernel<<<NB / 8, 256>>>(anchor, positive, labels);

    const int smem = 6 * TILE_BYTES;   // 208896 B
    cudaFuncSetAttribute(maxgram_sym, cudaFuncAttributeMaxDynamicSharedMemorySize, smem);
    maxgram_sym<<<GRID, 256, smem>>>();

    finalize_kernel<<<1, 256>>>(out);
}

// round 6
// speedup vs baseline: 5.6259x; 1.0220x over previous
#include <cuda_runtime.h>
#include <cuda_bf16.h>
#include <cstdint>

// Problem constants (fixed: B=8192, D=128)
#define NB 8192
#define ND 128
#define NTILE 64                    // 8192 / 128 tile rows
#define GRID 130
#define TPC 16                      // tiles per CTA: 130*16 = 2080
#define MARGIN 0.5f
#define STRB 272                    // padded row stride in bytes -> conflict-free ldmatrix
#define TILE_BYTES (128 * STRB)     // 34816 per 128x128 bf16 tile

// Device scratch (no allocation allowed)
__device__ __align__(16) __nv_bfloat16 g_ahi[NB * ND];
__device__ __align__(16) __nv_bfloat16 g_alo[NB * ND];
__device__ float g_posd[NB];
__device__ int   g_lab[NB];
__device__ int   g_maxbits[NB];

// ---------------------------------------------------------------------------
// helpers
// ---------------------------------------------------------------------------
__device__ __forceinline__ uint32_t smem_u32(const void* p) {
    uint32_t a;
    asm("{ .reg .u64 t; cvta.to.shared.u64 t, %1; cvt.u32.u64 %0, t; }" : "=r"(a) : "l"(p));
    return a;
}
__device__ __forceinline__ void cpasync16(uint32_t dst, const void* src) {
    asm volatile("cp.async.cg.shared.global [%0], [%1], 16;" :: "r"(dst), "l"(src));
}
__device__ __forceinline__ void mma16816(float* c, const uint32_t* a, const uint32_t* b) {
    asm volatile(
        "mma.sync.aligned.m16n8k16.row.col.f32.bf16.bf16.f32 "
        "{%0,%1,%2,%3}, {%4,%5,%6,%7}, {%8,%9}, {%0,%1,%2,%3};"
        : "+f"(c[0]), "+f"(c[1]), "+f"(c[2]), "+f"(c[3])
        : "r"(a[0]), "r"(a[1]), "r"(a[2]), "r"(a[3]), "r"(b[0]), "r"(b[1]));
}
__device__ __forceinline__ void ldsm4(uint32_t* r, uint32_t addr) {
    asm volatile("ldmatrix.sync.aligned.m8n8.x4.shared.b16 {%0,%1,%2,%3}, [%4];"
        : "=r"(r[0]), "=r"(r[1]), "=r"(r[2]), "=r"(r[3]) : "r"(addr));
}

// ---------------------------------------------------------------------------
// Kernel 1: normalize anchors -> bf16 hi/lo split; pos_dist; labels; init max.
// ---------------------------------------------------------------------------
__global__ void prep_kernel(const float* __restrict__ anchor,
                            const float* __restrict__ positive,
                            const int* __restrict__ labels) {
    int row  = (blockIdx.x * blockDim.x + threadIdx.x) >> 5;
    int lane = threadIdx.x & 31;
    if (row >= NB) return;

    float4 av = reinterpret_cast<const float4*>(anchor   + (size_t)row * ND)[lane];
    float4 pv = reinterpret_cast<const float4*>(positive + (size_t)row * ND)[lane];

    float sa = av.x*av.x + av.y*av.y + av.z*av.z + av.w*av.w;
    float sp = pv.x*pv.x + pv.y*pv.y + pv.z*pv.z + pv.w*pv.w;
    #pragma unroll
    for (int o = 16; o > 0; o >>= 1) {
        sa += __shfl_xor_sync(0xffffffffu, sa, o);
        sp += __shfl_xor_sync(0xffffffffu, sp, o);
    }
    float inva = 1.0f / fmaxf(sqrtf(sa), 1e-12f);
    float invp = 1.0f / fmaxf(sqrtf(sp), 1e-12f);

    float an[4] = {av.x*inva, av.y*inva, av.z*inva, av.w*inva};
    float pn[4] = {pv.x*invp, pv.y*invp, pv.z*invp, pv.w*invp};

    __nv_bfloat16 hi[4], lo[4];
    #pragma unroll
    for (int q = 0; q < 4; q++) {
        hi[q] = __float2bfloat16_rn(an[q]);
        lo[q] = __float2bfloat16_rn(an[q] - __bfloat162float(hi[q]));
    }
    size_t base = (size_t)row * ND + lane * 4;
    __nv_bfloat162 h01; h01.x = hi[0]; h01.y = hi[1];
    __nv_bfloat162 h23; h23.x = hi[2]; h23.y = hi[3];
    __nv_bfloat162 l01; l01.x = lo[0]; l01.y = lo[1];
    __nv_bfloat162 l23; l23.x = lo[2]; l23.y = lo[3];
    reinterpret_cast<__nv_bfloat162*>(g_ahi + base)[0] = h01;
    reinterpret_cast<__nv_bfloat162*>(g_ahi + base)[1] = h23;
    reinterpret_cast<__nv_bfloat162*>(g_alo + base)[0] = l01;
    reinterpret_cast<__nv_bfloat162*>(g_alo + base)[1] = l23;

    float d2 = 0.0f;
    #pragma unroll
    for (int q = 0; q < 4; q++) {
        float d = an[q] - pn[q];
        d2 = fmaf(d, d, d2);
    }
    #pragma unroll
    for (int o = 16; o > 0; o >>= 1)
        d2 += __shfl_xor_sync(0xffffffffu, d2, o);

    if (lane == 0) {
        g_posd[row]    = d2;
        g_lab[row]     = labels[row];
        g_maxbits[row] = 0;
    }
}

// ---------------------------------------------------------------------------
// Kernel 2: symmetric max-gram, ldmatrix + 512 threads.
// Warp grid 4(M) x 4(N): each warp owns 32 rows x 32 cols of the 128x128 tile.
// SMEM: [A hi][A lo][B0 hi][B0 lo][B1 hi][B1 lo], rows padded to 272 B.
// 130 CTAs x 16 triangular tiles = 2080 tiles, one wave.
// ---------------------------------------------------------------------------
__global__ void __launch_bounds__(512, 1) maxgram_sym() {
    extern __shared__ char dsm[];
    __shared__ int labJ[2][128];

    const int tid  = threadIdx.x;
    const int lane = tid & 31;
    const int wid  = tid >> 5;
    const int wm   = wid & 3;         // M quarter
    const int wn   = wid >> 2;        // N quarter
    const int g    = lane >> 2;
    const int q    = lane & 3;

    const uint32_t smb = smem_u32(dsm);

    // ldmatrix per-lane base addresses (byte offsets within a tile)
    // A x4 (16x16): lanes 0-15 -> rows, bit4 -> k-half (8 elems = 16 B)
    const uint32_t aoff = (uint32_t)(wm * 32 + (lane & 15)) * STRB + (uint32_t)(lane >> 4) * 16;
    // B x4 (16 cols x 16 k): bit4 -> col+8, bit3 -> k-half
    const uint32_t boff = (uint32_t)(wn * 32 + ((lane >> 4) << 3) + (lane & 7)) * STRB
                        + (uint32_t)((lane >> 3) & 1) * 16;

    // decode starting tile (triangular row-major)
    int L = blockIdx.x * TPC;
    int ti = 0, base = 0;
    while (base + (NTILE - ti) <= L) { base += NTILE - ti; ti++; }
    int tj = ti + (L - base);

    auto loadA = [&](int t) {
        const int i0 = t * 128;
        for (int idx = tid; idx < 2048; idx += 512) {
            int r = idx >> 4, c = idx & 15;
            uint32_t d = smb + r * STRB + c * 16;
            cpasync16(d,              g_ahi + (size_t)(i0 + r) * ND + c * 8);
            cpasync16(d + TILE_BYTES, g_alo + (size_t)(i0 + r) * ND + c * 8);
        }
    };
    auto loadB = [&](int t, int buf) {
        const int j0 = t * 128;
        uint32_t bb = smb + (2 + 2 * buf) * TILE_BYTES;
        for (int idx = tid; idx < 2048; idx += 512) {
            int r = idx >> 4, c = idx & 15;
            uint32_t d = bb + r * STRB + c * 16;
            cpasync16(d,              g_ahi + (size_t)(j0 + r) * ND + c * 8);
            cpasync16(d + TILE_BYTES, g_alo + (size_t)(j0 + r) * ND + c * 8);
        }
        if (tid < 128) labJ[buf][tid] = g_lab[j0 + tid];
    };

    int lr[2][2];
    auto loadLr = [&](int t) {
        #pragma unroll
        for (int mt = 0; mt < 2; mt++) {
            int r = t * 128 + wm * 32 + mt * 16 + g;
            lr[mt][0] = g_lab[r];
            lr[mt][1] = g_lab[r + 8];
        }
    };

    float mx[2][2];
    #pragma unroll
    for (int mt = 0; mt < 2; mt++) { mx[mt][0] = -3.0f; mx[mt][1] = -3.0f; }

    auto flushRows = [&](int t) {
        #pragma unroll
        for (int mt = 0; mt < 2; mt++)
            #pragma unroll
            for (int r = 0; r < 2; r++) {
                float v = mx[mt][r];
                v = fmaxf(v, __shfl_xor_sync(0xffffffffu, v, 1));
                v = fmaxf(v, __shfl_xor_sync(0xffffffffu, v, 2));
                if (q == 0)
                    atomicMax(&g_maxbits[t * 128 + wm * 32 + mt * 16 + g + r * 8],
                              __float_as_int(fmaxf(v + 2.0f, 0.0f)));
                mx[mt][r] = -3.0f;
            }
    };

    // prologue: first A + first B
    loadA(ti);
    loadB(tj, 0);
    asm volatile("cp.async.commit_group;");
    loadLr(ti);

    for (int n = 0; n < TPC; n++) {
        const int buf = n & 1;

        // next tile coordinates (triangular walk)
        int ti_n = ti, tj_n = tj + 1;
        if (tj_n == NTILE) { ti_n = ti + 1; tj_n = ti_n; }

        asm volatile("cp.async.wait_group 0;" ::: "memory");
        __syncthreads();

        if (n + 1 < TPC) {
            loadB(tj_n, buf ^ 1);
            asm volatile("cp.async.commit_group;");
        }

        // ---- compute tile (ti, tj) ----
        const uint32_t Ahi = smb + aoff;
        const uint32_t Bhi = smb + (2 + 2 * buf) * TILE_BYTES + boff;

        float acc[2][4][4];
        #pragma unroll
        for (int mt = 0; mt < 2; mt++)
            #pragma unroll
            for (int nt = 0; nt < 4; nt++)
                #pragma unroll
                for (int e = 0; e < 4; e++) acc[mt][nt][e] = 0.0f;

        #pragma unroll
        for (int ks = 0; ks < 8; ks++) {
            const uint32_t ko = ks * 32;

            uint32_t ah[2][4], al[2][4], bh[4][2], bl[4][2];
            #pragma unroll
            for (int mt = 0; mt < 2; mt++) {
                ldsm4(ah[mt], Ahi + mt * (16 * STRB) + ko);
                ldsm4(al[mt], Ahi + TILE_BYTES + mt * (16 * STRB) + ko);
            }
            #pragma unroll
            for (int p = 0; p < 2; p++) {
                uint32_t rh[4], rl[4];
                ldsm4(rh, Bhi + p * (16 * STRB) + ko);
                ldsm4(rl, Bhi + TILE_BYTES + p * (16 * STRB) + ko);
                bh[2*p][0] = rh[0]; bh[2*p][1] = rh[1];
                bh[2*p+1][0] = rh[2]; bh[2*p+1][1] = rh[3];
                bl[2*p][0] = rl[0]; bl[2*p][1] = rl[1];
                bl[2*p+1][0] = rl[2]; bl[2*p+1][1] = rl[3];
            }
            #pragma unroll
            for (int mt = 0; mt < 2; mt++)
                #pragma unroll
                for (int nt = 0; nt < 4; nt++) {
                    mma16816(acc[mt][nt], ah[mt], bh[nt]);   // hi*hi
                    mma16816(acc[mt][nt], ah[mt], bl[nt]);   // hi*lo
                    mma16816(acc[mt][nt], al[mt], bh[nt]);   // lo*hi
                }
        }

        // ---- epilogue: mask, row-max, column-max ----
        float cmax[4][2];
        #pragma unroll
        for (int nt = 0; nt < 4; nt++) { cmax[nt][0] = -3.0f; cmax[nt][1] = -3.0f; }

        #pragma unroll
        for (int nt = 0; nt < 4; nt++) {
            int c0 = wn * 32 + nt * 8 + q * 2;
            int l0 = labJ[buf][c0], l1 = labJ[buf][c0 + 1];
            #pragma unroll
            for (int mt = 0; mt < 2; mt++) {
                float v0 = (l0 == lr[mt][0]) ? -3.0f : acc[mt][nt][0];
                float v1 = (l1 == lr[mt][0]) ? -3.0f : acc[mt][nt][1];
                float v2 = (l0 == lr[mt][1]) ? -3.0f : acc[mt][nt][2];
                float v3 = (l1 == lr[mt][1]) ? -3.0f : acc[mt][nt][3];
                mx[mt][0] = fmaxf(mx[mt][0], fmaxf(v0, v1));
                mx[mt][1] = fmaxf(mx[mt][1], fmaxf(v2, v3));
                cmax[nt][0] = fmaxf(cmax[nt][0], fmaxf(v0, v2));
                cmax[nt][1] = fmaxf(cmax[nt][1], fmaxf(v1, v3));
            }
        }

        if (ti != tj) {
            #pragma unroll
            for (int nt = 0; nt < 4; nt++)
                #pragma unroll
                for (int e = 0; e < 2; e++) {
                    float v = cmax[nt][e];
                    v = fmaxf(v, __shfl_xor_sync(0xffffffffu, v, 4));
                    v = fmaxf(v, __shfl_xor_sync(0xffffffffu, v, 8));
                    v = fmaxf(v, __shfl_xor_sync(0xffffffffu, v, 16));
                    if (g == 0)
                        atomicMax(&g_maxbits[tj * 128 + wn * 32 + nt * 8 + q * 2 + e],
                                  __float_as_int(fmaxf(v + 2.0f, 0.0f)));
                }
        }

        if (n + 1 < TPC) {
            if (ti_n != ti) {
                flushRows(ti);
                __syncthreads();          // all warps done reading A
                loadA(ti_n);
                asm volatile("cp.async.commit_group;");
                loadLr(ti_n);
            }
            ti = ti_n; tj = tj_n;
        }
    }
    flushRows(ti);
}

// ---------------------------------------------------------------------------
// Kernel 3: final loss reduction.
// ---------------------------------------------------------------------------
__global__ void finalize_kernel(float* __restrict__ out) {
    __shared__ float red[256];
    float s = 0.0f;
    for (int i = threadIdx.x; i < NB; i += 256) {
        float gmax = __int_as_float(g_maxbits[i]) - 2.0f;
        float neg  = fmaxf(2.0f - 2.0f * gmax, 0.0f);
        float l    = g_posd[i] - neg + MARGIN;
        s += fmaxf(l, 0.0f);
    }
    red[threadIdx.x] = s;
    __syncthreads();
    #pragma unroll
    for (int stride = 128; stride > 0; stride >>= 1) {
        if (threadIdx.x < stride) red[threadIdx.x] += red[threadIdx.x + stride];
        __syncthreads();
    }
    if (threadIdx.x == 0) out[0] = red[0] / (float)NB;
}

extern "C" void kernel_launch(void* const* d_in, const int* in_sizes, int n_in,
                              void* d_out, int out_size) {
    const float* anchor   = (const float*)d_in[0];
    const float* positive = (const float*)d_in[1];
    const int*   labels   = (const int*)d_in[2];   // JAX x64 disabled: int64 -> int32
    float*       out      = (float*)d_out;

    prep_kernel<<<NB / 8, 256>>>(anchor, positive, labels);

    const int smem = 6 * TILE_BYTES;   // 208896 B
    cudaFuncSetAttribute(maxgram_sym, cudaFuncAttributeMaxDynamicSharedMemorySize, smem);
    maxgram_sym<<<GRID, 512, smem>>>();

    finalize_kernel<<<1, 256>>>(out);
}

// round 7
// speedup vs baseline: 11.6331x; 2.0678x over previous
#include <cuda_runtime.h>
#include <cuda_fp16.h>
#include <cstdint>

// Problem constants (fixed: B=8192, D=128)
#define NB 8192
#define ND 128
#define NTILE 64                    // 8192 / 128 tile rows
#define GRID 260
#define TPC 8                       // tiles per CTA: 260*8 = 2080
#define MARGIN 0.5f
#define STRB 272                    // padded row stride in bytes -> conflict-free ldmatrix
#define TILE_BYTES (128 * STRB)     // 34816 per 128x128 fp16 tile

// Device scratch (no allocation allowed)
__device__ __align__(16) __half g_af16[NB * ND];
__device__ float g_posd[NB];
__device__ int   g_lab[NB];
__device__ int   g_maxbits[NB];

// ---------------------------------------------------------------------------
// helpers
// ---------------------------------------------------------------------------
__device__ __forceinline__ uint32_t smem_u32(const void* p) {
    uint32_t a;
    asm("{ .reg .u64 t; cvta.to.shared.u64 t, %1; cvt.u32.u64 %0, t; }" : "=r"(a) : "l"(p));
    return a;
}
__device__ __forceinline__ void cpasync16(uint32_t dst, const void* src) {
    asm volatile("cp.async.cg.shared.global [%0], [%1], 16;" :: "r"(dst), "l"(src));
}
__device__ __forceinline__ void mma16816(float* c, const uint32_t* a, const uint32_t* b) {
    asm volatile(
        "mma.sync.aligned.m16n8k16.row.col.f32.f16.f16.f32 "
        "{%0,%1,%2,%3}, {%4,%5,%6,%7}, {%8,%9}, {%0,%1,%2,%3};"
        : "+f"(c[0]), "+f"(c[1]), "+f"(c[2]), "+f"(c[3])
        : "r"(a[0]), "r"(a[1]), "r"(a[2]), "r"(a[3]), "r"(b[0]), "r"(b[1]));
}
__device__ __forceinline__ void ldsm4(uint32_t* r, uint32_t addr) {
    asm volatile("ldmatrix.sync.aligned.m8n8.x4.shared.b16 {%0,%1,%2,%3}, [%4];"
        : "=r"(r[0]), "=r"(r[1]), "=r"(r[2]), "=r"(r[3]) : "r"(addr));
}

// ---------------------------------------------------------------------------
// Kernel 1: normalize anchors -> fp16; pos_dist; labels; init max.
// ---------------------------------------------------------------------------
__global__ void prep_kernel(const float* __restrict__ anchor,
                            const float* __restrict__ positive,
                            const int* __restrict__ labels) {
    int row  = (blockIdx.x * blockDim.x + threadIdx.x) >> 5;
    int lane = threadIdx.x & 31;
    if (row >= NB) return;

    float4 av = reinterpret_cast<const float4*>(anchor   + (size_t)row * ND)[lane];
    float4 pv = reinterpret_cast<const float4*>(positive + (size_t)row * ND)[lane];

    float sa = av.x*av.x + av.y*av.y + av.z*av.z + av.w*av.w;
    float sp = pv.x*pv.x + pv.y*pv.y + pv.z*pv.z + pv.w*pv.w;
    #pragma unroll
    for (int o = 16; o > 0; o >>= 1) {
        sa += __shfl_xor_sync(0xffffffffu, sa, o);
        sp += __shfl_xor_sync(0xffffffffu, sp, o);
    }
    float inva = 1.0f / fmaxf(sqrtf(sa), 1e-12f);
    float invp = 1.0f / fmaxf(sqrtf(sp), 1e-12f);

    float an[4] = {av.x*inva, av.y*inva, av.z*inva, av.w*inva};
    float pn[4] = {pv.x*invp, pv.y*invp, pv.z*invp, pv.w*invp};

    __half2 h01; h01.x = __float2half_rn(an[0]); h01.y = __float2half_rn(an[1]);
    __half2 h23; h23.x = __float2half_rn(an[2]); h23.y = __float2half_rn(an[3]);
    size_t base = (size_t)row * ND + lane * 4;
    reinterpret_cast<__half2*>(g_af16 + base)[0] = h01;
    reinterpret_cast<__half2*>(g_af16 + base)[1] = h23;

    float d2 = 0.0f;
    #pragma unroll
    for (int q = 0; q < 4; q++) {
        float d = an[q] - pn[q];
        d2 = fmaf(d, d, d2);
    }
    #pragma unroll
    for (int o = 16; o > 0; o >>= 1)
        d2 += __shfl_xor_sync(0xffffffffu, d2, o);

    if (lane == 0) {
        g_posd[row]    = d2;
        g_lab[row]     = labels[row];
        g_maxbits[row] = 0;
    }
}

// ---------------------------------------------------------------------------
// Kernel 2: symmetric max-gram, single-term fp16 mma.sync.
// 8 warps, 2(M) x 4(N): warp tile 64 rows x 32 cols. ldmatrix fragments.
// SMEM: [A][B0][B1], rows padded to 272 B. 260 CTAs x 8 tiles (occupancy 2).
// ---------------------------------------------------------------------------
__global__ void __launch_bounds__(256, 2) maxgram_sym() {
    extern __shared__ char dsm[];
    __shared__ int labJ[2][128];

    const int tid  = threadIdx.x;
    const int lane = tid & 31;
    const int wid  = tid >> 5;
    const int wm   = wid & 1;         // M half (64 rows)
    const int wn   = wid >> 1;        // N quarter (32 cols)
    const int g    = lane >> 2;
    const int q    = lane & 3;

    const uint32_t smb = smem_u32(dsm);

    // ldmatrix per-lane base byte offsets within a tile
    const uint32_t aoff = (uint32_t)(wm * 64 + (lane & 15)) * STRB + (uint32_t)(lane >> 4) * 16;
    const uint32_t boff = (uint32_t)(wn * 32 + ((lane >> 4) << 3) + (lane & 7)) * STRB
                        + (uint32_t)((lane >> 3) & 1) * 16;

    // decode starting tile (triangular row-major)
    int L = blockIdx.x * TPC;
    int ti = 0, base = 0;
    while (base + (NTILE - ti) <= L) { base += NTILE - ti; ti++; }
    int tj = ti + (L - base);

    auto loadA = [&](int t) {
        const int i0 = t * 128;
        for (int idx = tid; idx < 2048; idx += 256) {
            int r = idx >> 4, c = idx & 15;
            cpasync16(smb + r * STRB + c * 16,
                      g_af16 + (size_t)(i0 + r) * ND + c * 8);
        }
    };
    auto loadB = [&](int t, int buf) {
        const int j0 = t * 128;
        uint32_t bb = smb + (1 + buf) * TILE_BYTES;
        for (int idx = tid; idx < 2048; idx += 256) {
            int r = idx >> 4, c = idx & 15;
            cpasync16(bb + r * STRB + c * 16,
                      g_af16 + (size_t)(j0 + r) * ND + c * 8);
        }
        if (tid < 128) labJ[buf][tid] = g_lab[j0 + tid];
    };

    int lr[4][2];
    auto loadLr = [&](int t) {
        #pragma unroll
        for (int mt = 0; mt < 4; mt++) {
            int r = t * 128 + wm * 64 + mt * 16 + g;
            lr[mt][0] = g_lab[r];
            lr[mt][1] = g_lab[r + 8];
        }
    };

    float mx[4][2];
    #pragma unroll
    for (int mt = 0; mt < 4; mt++) { mx[mt][0] = -3.0f; mx[mt][1] = -3.0f; }

    auto flushRows = [&](int t) {
        #pragma unroll
        for (int mt = 0; mt < 4; mt++)
            #pragma unroll
            for (int r = 0; r < 2; r++) {
                float v = mx[mt][r];
                v = fmaxf(v, __shfl_xor_sync(0xffffffffu, v, 1));
                v = fmaxf(v, __shfl_xor_sync(0xffffffffu, v, 2));
                if (q == 0)
                    atomicMax(&g_maxbits[t * 128 + wm * 64 + mt * 16 + g + r * 8],
                              __float_as_int(fmaxf(v + 2.0f, 0.0f)));
                mx[mt][r] = -3.0f;
            }
    };

    // prologue
    loadA(ti);
    loadB(tj, 0);
    asm volatile("cp.async.commit_group;");
    loadLr(ti);

    for (int n = 0; n < TPC; n++) {
        const int buf = n & 1;

        int ti_n = ti, tj_n = tj + 1;
        if (tj_n == NTILE) { ti_n = ti + 1; tj_n = ti_n; }

        asm volatile("cp.async.wait_group 0;" ::: "memory");
        __syncthreads();

        if (n + 1 < TPC) {
            loadB(tj_n, buf ^ 1);
            asm volatile("cp.async.commit_group;");
        }

        // ---- compute tile (ti, tj): single fp16 term ----
        const uint32_t Abase = smb + aoff;
        const uint32_t Bbase = smb + (1 + buf) * TILE_BYTES + boff;

        float acc[4][4][4];
        #pragma unroll
        for (int mt = 0; mt < 4; mt++)
            #pragma unroll
            for (int nt = 0; nt < 4; nt++)
                #pragma unroll
                for (int e = 0; e < 4; e++) acc[mt][nt][e] = 0.0f;

        #pragma unroll
        for (int ks = 0; ks < 8; ks++) {
            const uint32_t ko = ks * 32;

            uint32_t a[4][4], b[4][2];
            #pragma unroll
            for (int mt = 0; mt < 4; mt++)
                ldsm4(a[mt], Abase + mt * (16 * STRB) + ko);
            #pragma unroll
            for (int p = 0; p < 2; p++) {
                uint32_t rb[4];
                ldsm4(rb, Bbase + p * (16 * STRB) + ko);
                b[2*p][0] = rb[0]; b[2*p][1] = rb[1];
                b[2*p+1][0] = rb[2]; b[2*p+1][1] = rb[3];
            }
            #pragma unroll
            for (int mt = 0; mt < 4; mt++)
                #pragma unroll
                for (int nt = 0; nt < 4; nt++)
                    mma16816(acc[mt][nt], a[mt], b[nt]);
        }

        // ---- epilogue: mask, row-max, column-max ----
        float cmax[4][2];
        #pragma unroll
        for (int nt = 0; nt < 4; nt++) { cmax[nt][0] = -3.0f; cmax[nt][1] = -3.0f; }

        #pragma unroll
        for (int nt = 0; nt < 4; nt++) {
            int c0 = wn * 32 + nt * 8 + q * 2;
            int l0 = labJ[buf][c0], l1 = labJ[buf][c0 + 1];
            #pragma unroll
            for (int mt = 0; mt < 4; mt++) {
                float v0 = (l0 == lr[mt][0]) ? -3.0f : acc[mt][nt][0];
                float v1 = (l1 == lr[mt][0]) ? -3.0f : acc[mt][nt][1];
                float v2 = (l0 == lr[mt][1]) ? -3.0f : acc[mt][nt][2];
                float v3 = (l1 == lr[mt][1]) ? -3.0f : acc[mt][nt][3];
                mx[mt][0] = fmaxf(mx[mt][0], fmaxf(v0, v1));
                mx[mt][1] = fmaxf(mx[mt][1], fmaxf(v2, v3));
                cmax[nt][0] = fmaxf(cmax[nt][0], fmaxf(v0, v2));
                cmax[nt][1] = fmaxf(cmax[nt][1], fmaxf(v1, v3));
            }
        }

        if (ti != tj) {
            #pragma unroll
            for (int nt = 0; nt < 4; nt++)
                #pragma unroll
                for (int e = 0; e < 2; e++) {
                    float v = cmax[nt][e];
                    v = fmaxf(v, __shfl_xor_sync(0xffffffffu, v, 4));
                    v = fmaxf(v, __shfl_xor_sync(0xffffffffu, v, 8));
                    v = fmaxf(v, __shfl_xor_sync(0xffffffffu, v, 16));
                    if (g == 0)
                        atomicMax(&g_maxbits[tj * 128 + wn * 32 + nt * 8 + q * 2 + e],
                                  __float_as_int(fmaxf(v + 2.0f, 0.0f)));
                }
        }

        if (n + 1 < TPC) {
            if (ti_n != ti) {
                flushRows(ti);
                __syncthreads();          // all warps done reading A
                loadA(ti_n);
                asm volatile("cp.async.commit_group;");
                loadLr(ti_n);
            }
            ti = ti_n; tj = tj_n;
        }
    }
    flushRows(ti);
}

// ---------------------------------------------------------------------------
// Kernel 3: final loss reduction.
// ---------------------------------------------------------------------------
__global__ void finalize_kernel(float* __restrict__ out) {
    __shared__ float red[256];
    float s = 0.0f;
    for (int i = threadIdx.x; i < NB; i += 256) {
        float gmax = __int_as_float(g_maxbits[i]) - 2.0f;
        float neg  = fmaxf(2.0f - 2.0f * gmax, 0.0f);
        float l    = g_posd[i] - neg + MARGIN;
        s += fmaxf(l, 0.0f);
    }
    red[threadIdx.x] = s;
    __syncthreads();
    #pragma unroll
    for (int stride = 128; stride > 0; stride >>= 1) {
        if (threadIdx.x < stride) red[threadIdx.x] += red[threadIdx.x + stride];
        __syncthreads();
    }
    if (threadIdx.x == 0) out[0] = red[0] / (float)NB;
}

extern "C" void kernel_launch(void* const* d_in, const int* in_sizes, int n_in,
                              void* d_out, int out_size) {
    const float* anchor   = (const float*)d_in[0];
    const float* positive = (const float*)d_in[1];
    const int*   labels   = (const int*)d_in[2];   // JAX x64 disabled: int64 -> int32
    float*       out      = (float*)d_out;

    prep_kernel<<<NB / 8, 256>>>(anchor, positive, labels);

    const int smem = 3 * TILE_BYTES;   // 104448 B -> 2 CTAs/SM
    cudaFuncSetAttribute(maxgram_sym, cudaFuncAttributeMaxDynamicSharedMemorySize, smem);
    maxgram_sym<<<GRID, 256, smem>>>();

    finalize_kernel<<<1, 256>>>(out);
}